// round 12
// baseline (speedup 1.0000x reference)
#include <cuda_runtime.h>
#include <cstdint>
#include <math.h>

// Problem dimensions
#define BB 256
#define TT 64
#define EE 1024
#define AA 6
#define DD 256
#define SS 32
#define CC 32
#define HH 256
#define SDIM 1024
#define OUTW 4352   // 4*SD + D per (b,t)

#define NGUM (2 * TT * BB * SS * CC)   // 4,194,304 elements (16 MB)

// Background items per step: 256 epart K-quarters + 16 gumbel eighths
#define NQITEMS 272
#define K1_GEMM 96      // gates tiles in kernel 1
#define K1_BG   52      // bg items hosted by kernel 1
#define K2_GEMM 128     // out tiles in kernel 2
#define K2_BG   (NQITEMS - K1_BG)   // 220

// ---------------- device scratch (no allocation allowed) ----------------
__device__ float g_gumbel[NGUM];
__device__ float g_deterA[BB * DD];                 // ping-pong deter buffers
__device__ float g_deterB[BB * DD];
__device__ float g_x[BB * HH];                      // GRU input x(t)
__device__ float g_gi[BB * 768];
__device__ float g_gh[BB * 768];
__device__ float g_dpart[BB * SDIM];                // deter part of post logits
// epart K-quarters, T-MAJOR: g_epQ[c][(t*BB+b)*SDIM + n], c = k-quarter
__device__ float g_epQ[4][(long)TT * BB * SDIM];    // 4 x 67 MB
__device__ unsigned g_c1, g_c2;                     // monotonic phase counters

// ---------------- shared workspace --------------------------------------
struct GemmSmem {
    float As[2][16][64 + 4];
    float Bs[2][16][64];
};

// ---------------- double-buffered fp32 tiled GEMM core ------------------
// C[m,n] = sum_{k in [k0,k0+kcnt)} A(m,k)*B[k,n_off+n] (+bias).
// Pure ascending-K per-element accumulation.
template<class AL>
__device__ __forceinline__ void gemm_db64(
    GemmSmem& ws, AL aload, const float* __restrict__ Bm, int ldb,
    int m_off, int n_off, int k0, int kcnt,
    float* __restrict__ C, long ldc, const float* __restrict__ bias)
{
    constexpr int BM = 64, BN = 64, BK = 16, NTHR = 256, TM = 4, TN = 4;
    const int tid = threadIdx.x;
    const int tx = tid % (BN / TN);
    const int ty = tid / (BN / TN);
    constexpr int ALD = BM * BK / NTHR;   // 4
    constexpr int BLD = BN * BK / NTHR;   // 4
    const int amk = tid % BK;
    const int am0 = tid / BK;
    const int bn  = tid % BN;
    const int bk0 = tid / BN;

    float rA[ALD], rB[BLD];
    float acc[TM][TN];
#pragma unroll
    for (int i = 0; i < TM; i++)
#pragma unroll
        for (int j = 0; j < TN; j++) acc[i][j] = 0.f;

    const int NT = kcnt / BK;

#pragma unroll
    for (int j = 0; j < ALD; j++)
        rA[j] = aload(m_off + am0 + j * (NTHR / BK), k0 + amk);
#pragma unroll
    for (int j = 0; j < BLD; j++)
        rB[j] = Bm[(long)(k0 + bk0 + j * (NTHR / BN)) * ldb + n_off + bn];
#pragma unroll
    for (int j = 0; j < ALD; j++) ws.As[0][amk][am0 + j * (NTHR / BK)] = rA[j];
#pragma unroll
    for (int j = 0; j < BLD; j++) ws.Bs[0][bk0 + j * (NTHR / BN)][bn] = rB[j];
    __syncthreads();

    for (int kt = 0; kt < NT; kt++) {
        int cur = kt & 1;
        if (kt + 1 < NT) {
            int kb = k0 + (kt + 1) * BK;
#pragma unroll
            for (int j = 0; j < ALD; j++)
                rA[j] = aload(m_off + am0 + j * (NTHR / BK), kb + amk);
#pragma unroll
            for (int j = 0; j < BLD; j++)
                rB[j] = Bm[(long)(kb + bk0 + j * (NTHR / BN)) * ldb + n_off + bn];
        }
#pragma unroll
        for (int kk = 0; kk < BK; kk++) {
            float4 av = *reinterpret_cast<const float4*>(&ws.As[cur][kk][ty * TM]);
            float4 bv = *reinterpret_cast<const float4*>(&ws.Bs[cur][kk][tx * TN]);
            float am[4] = {av.x, av.y, av.z, av.w};
            float bn_[4] = {bv.x, bv.y, bv.z, bv.w};
#pragma unroll
            for (int i = 0; i < TM; i++)
#pragma unroll
                for (int j = 0; j < TN; j++) acc[i][j] += am[i] * bn_[j];
        }
        if (kt + 1 < NT) {
            int nb = cur ^ 1;
#pragma unroll
            for (int j = 0; j < ALD; j++) ws.As[nb][amk][am0 + j * (NTHR / BK)] = rA[j];
#pragma unroll
            for (int j = 0; j < BLD; j++) ws.Bs[nb][bk0 + j * (NTHR / BN)][bn] = rB[j];
            __syncthreads();
        }
    }
    __syncthreads();
#pragma unroll
    for (int i = 0; i < TM; i++) {
        int m = m_off + ty * TM + i;
#pragma unroll
        for (int j = 0; j < TN; j++) {
            int n = n_off + tx * TN + j;
            float v = acc[i][j];
            if (bias) v += bias[n];
            C[(long)m * ldc + n] = v;
        }
    }
}

// ---------------- A-loaders ----------------------------------------------
struct GiL {
    __device__ float operator()(int m, int k) const { return g_x[m * HH + k]; }
};
struct GhL {
    const float* isf; const float* dold; int t;
    __device__ float operator()(int m, int k) const {
        return dold[m * DD + k] * (1.0f - isf[m * TT + t]);
    }
};
struct DetP {
    const float* d;
    __device__ float operator()(int m, int k) const { return d[m * DD + k]; }
};
struct EpartL {
    const float* E;
    __device__ float operator()(int rho, int k) const {
        int t = rho >> 8, b = rho & 255;
        return E[((long)b * TT + t) * EE + k];
    }
};

// ---------------- JAX threefry2x32 gumbel (partitionable) ----------------
__device__ __forceinline__ uint32_t rotl32(uint32_t v, int r) {
    return (v << r) | (v >> (32 - r));
}
__device__ __forceinline__ float bits_to_gumbel(uint32_t b) {
    float u = __uint_as_float((b >> 9) | 0x3f800000u) - 1.0f;
    const float tinyv = 1.17549435e-38f;
    u = fmaxf(u, tinyv);
    double inner = -log((double)u);
    float innerf = (float)inner;
    double outer = -log((double)innerf);
    return (float)outer;
}
__device__ __forceinline__ float gumbel_elem(uint32_t gidx) {
    uint32_t x0 = 0u, x1 = gidx;
    const uint32_t ks0 = 0u, ks1 = 42u, ks2 = 0x1BD11BDAu ^ 0u ^ 42u;
    x0 += ks0; x1 += ks1;
#define TF_R4(a, b, c, d)                                   \
    x0 += x1; x1 = rotl32(x1, a); x1 ^= x0;                 \
    x0 += x1; x1 = rotl32(x1, b); x1 ^= x0;                 \
    x0 += x1; x1 = rotl32(x1, c); x1 ^= x0;                 \
    x0 += x1; x1 = rotl32(x1, d); x1 ^= x0;
    TF_R4(13, 15, 26, 6);  x0 += ks1; x1 += ks2 + 1u;
    TF_R4(17, 29, 16, 24); x0 += ks2; x1 += ks0 + 2u;
    TF_R4(13, 15, 26, 6);  x0 += ks0; x1 += ks1 + 3u;
    TF_R4(17, 29, 16, 24); x0 += ks1; x1 += ks2 + 4u;
    TF_R4(13, 15, 26, 6);  x0 += ks2; x1 += ks0 + 5u;
#undef TF_R4
    return bits_to_gumbel(x0 ^ x1);
}

// ---------------- precise transcendentals --------------------------------
__device__ __forceinline__ float sigm_precise(float x) {
    return (float)(1.0 / (1.0 + exp((double)(-x))));
}
__device__ __forceinline__ float tanh_precise(float x) {
    return (float)tanh((double)x);
}

// ---------------- background item executor -------------------------------
// Item i for step t1: i<256 -> epart K-quarter; else gumbel eighth.
__device__ __forceinline__ void run_bg_item(GemmSmem& ws, int t1, int i,
                                            const float* embed, const float* Woo) {
    if (i < 256) {
        int c = i & 3;            // k-quarter -> buffer c
        int tau = i >> 2;         // tile 0..63: rows (tau&3)*64, cols (tau>>2)*64
        gemm_db64(ws, EpartL{embed}, Woo + (long)DD * SDIM, SDIM,
                  t1 * BB + (tau & 3) * 64, (tau >> 2) * 64,
                  c * 256, 256, g_epQ[c], SDIM, nullptr);
    } else {
        int r = i - 256;          // 0..15
        int draw = r >> 3, eighth = r & 7;
        unsigned base = (unsigned)(draw * TT + t1) * 262144u
                      + (unsigned)eighth * 32768u;
        unsigned tid = threadIdx.x;
#pragma unroll 4
        for (int j = 0; j < 128; j++) {
            unsigned gidx = base + (unsigned)j * 256u + tid;
            g_gumbel[gidx] = gumbel_elem(gidx);
        }
    }
}

// ---------------- intra-kernel phase barrier (monotonic) -----------------
__device__ __forceinline__ void phase_barrier(unsigned* ctr, unsigned tgt) {
    __syncthreads();
    if (threadIdx.x == 0) {
        __threadfence();
        atomicAdd(ctr, 1u);
        volatile unsigned* p = ctr;
        while (*p < tgt) __nanosleep(32);
    }
    __syncthreads();
}

// ---------------- init: deter=0, x(0), counters --------------------------
__global__ void k_init(const float* __restrict__ action, const float* __restrict__ W1,
                       const float* __restrict__ b1) {
    int i = blockIdx.x * blockDim.x + threadIdx.x;   // grid 256x256
    g_deterA[i] = 0.f;
    if (i < BB * HH) {
        int b = i >> 8, col = i & 255;
        float c3 = 0.f;
#pragma unroll
        for (int a = 0; a < AA; a++)
            c3 = fmaf(action[(long)b * TT * AA + a], W1[(SDIM + a) * HH + col], c3);
        g_x[b * HH + col] = b1[col] + c3;
    }
    if (i == 0) { g_c1 = 0u; g_c2 = 0u; }
}

// ---------------- prologue for t=0 (grid = NQITEMS) ----------------------
__global__ void __launch_bounds__(256)
k_pre(const float* __restrict__ embed, const float* __restrict__ Woo) {
    __shared__ GemmSmem ws;
    run_bg_item(ws, 0, blockIdx.x, embed, Woo);
}

// ---------------- K1: gates GEMMs + GRU  (+ bg items) --------------------
__global__ void __launch_bounds__(256)
k_step1(const float* __restrict__ embed, const float* __restrict__ isf,
        const float* __restrict__ Wih, const float* __restrict__ bih,
        const float* __restrict__ Whh, const float* __restrict__ bhh,
        const float* __restrict__ Woo,
        float* __restrict__ out, int t)
{
    __shared__ GemmSmem ws;
    const int bid = blockIdx.x;
    const int tid = threadIdx.x;
    const float* dold = (t & 1) ? g_deterB : g_deterA;
    float*       dnew = (t & 1) ? g_deterA : g_deterB;

    if (bid >= K1_GEMM) {               // bg blocks: item for t+1, no barrier
        if (t + 1 < TT) run_bg_item(ws, t + 1, bid - K1_GEMM, embed, Woo);
        return;
    }
    // gates GEMM: 96 tiles (gi 48 | gh 48)
    {
        int bz = bid / 48, rem = bid % 48, by = rem / 12, bx = rem % 12;
        if (bz == 0)
            gemm_db64(ws, GiL{}, Wih, 768, by * 64, bx * 64, 0, DD, g_gi, 768, bih);
        else
            gemm_db64(ws, GhL{isf, dold, t}, Whh, 768, by * 64, bx * 64, 0, DD,
                      g_gh, 768, bhh);
    }
    phase_barrier(&g_c1, (unsigned)(t + 1) * K1_GEMM);

    // GRU (exact R7 math); cross-block same-launch reads via __ldcg
    for (int base = bid * 256; base < BB * DD; base += K1_GEMM * 256) {
        int i = base + tid;
        if (i < BB * DD) {
            int b = i >> 8, d = i & 255;
            float ir = __ldcg(&g_gi[b * 768 + d]);
            float iz = __ldcg(&g_gi[b * 768 + 256 + d]);
            float in_ = __ldcg(&g_gi[b * 768 + 512 + d]);
            float hr = __ldcg(&g_gh[b * 768 + d]);
            float hz = __ldcg(&g_gh[b * 768 + 256 + d]);
            float hn = __ldcg(&g_gh[b * 768 + 512 + d]);
            float r = sigm_precise(ir + hr);
            float z = sigm_precise(iz + hz);
            float n = tanh_precise(in_ + r * hn);
            float h = dold[i] * (1.0f - isf[b * TT + t]);
            float nd = (1.0f - z) * n + z * h;
            dnew[i] = nd;
            out[((long)b * TT + t) * OUTW + 2048 + d] = nd;
        }
    }
}

// ---------------- K2: out GEMMs + sample + x-feedback (+ bg items) -------
__global__ void __launch_bounds__(256)
k_step2(const float* __restrict__ embed, const float* __restrict__ isf,
        const float* __restrict__ action,
        const float* __restrict__ W1, const float* __restrict__ b1,
        const float* __restrict__ Wio, const float* __restrict__ bio,
        const float* __restrict__ Woo, const float* __restrict__ boo,
        float* __restrict__ out, int t)
{
    __shared__ GemmSmem ws;
    __shared__ int sidx[SS];
    const int bid = blockIdx.x;
    const int tid = threadIdx.x;
    const int lane = tid & 31, w = tid >> 5;
    const float* dnew = (t & 1) ? g_deterA : g_deterB;

    if (bid >= K2_GEMM) {               // bg blocks: item for t+1, no barrier
        if (t + 1 < TT) run_bg_item(ws, t + 1, K1_BG + (bid - K2_GEMM), embed, Woo);
        return;
    }
    // out GEMMs: 128 tiles (prior 64 | dpart 64)
    {
        int bz = bid / 64, rem = bid % 64, by = rem / 16, bx = rem % 16;
        if (bz == 0)
            gemm_db64(ws, DetP{dnew}, Wio, SDIM, by * 64, bx * 64, 0, DD,
                      out + (long)t * OUTW + 2304, (long)TT * OUTW, bio);
        else
            gemm_db64(ws, DetP{dnew}, Woo, SDIM, by * 64, bx * 64, 0, DD,
                      g_dpart, SDIM, nullptr);
    }
    phase_barrier(&g_c2, (unsigned)(t + 1) * K2_GEMM);

    // sample: 4 units per block; units u = bid, bid+128, bid+256, bid+384
#pragma unroll
    for (int uu = 0; uu < 4; uu++) {
        int u = bid + uu * K2_GEMM;
        int draw = u >> 8, b = u & 255;
        long obase = ((long)b * TT + t) * OUTW;
#pragma unroll
        for (int qq = 0; qq < 4; qq++) {
            int g = w * 4 + qq;
            int col = g * 32 + lane;
            float lv;
            if (draw == 0) {
                lv = __ldcg(&out[obase + 2304 + col]);
            } else {
                long ei = ((long)t * BB + b) * SDIM + col;
                float ep = ((g_epQ[0][ei] + g_epQ[1][ei]) + g_epQ[2][ei]) + g_epQ[3][ei];
                lv = (__ldcg(&g_dpart[b * SDIM + col]) + ep) + boo[col];
                out[obase + col] = lv;
            }
            float gum = g_gumbel[(((long)draw * TT + t) * BB + b) * SDIM + col];
            float v = lv + gum;
            int idx = lane;
#pragma unroll
            for (int off = 16; off > 0; off >>= 1) {
                float v2 = __shfl_xor_sync(0xffffffffu, v, off);
                int i2 = __shfl_xor_sync(0xffffffffu, idx, off);
                if (v2 > v || (v2 == v && i2 < idx)) { v = v2; idx = i2; }
            }
            float oh = (lane == idx) ? 1.0f : 0.0f;
            out[obase + (draw ? 1024 : 3328) + col] = oh;
            if (draw && lane == 0) sidx[g] = idx;
        }
        if (draw == 1 && t + 1 < TT) {
            __syncthreads();
            int col = tid;
            float mask = 1.0f - isf[b * TT + (t + 1)];
            float c0 = 0.f, c1 = 0.f, c2 = 0.f, c3 = 0.f;
            int i8 = sidx[8], i25 = sidx[25];
#pragma unroll
            for (int s2 = 0; s2 < 8; s2++)
                c0 = fmaf(mask, W1[(s2 * 32 + sidx[s2]) * HH + col], c0);
            {
                float wv = W1[(8 * 32 + i8) * HH + col];
                if (i8 < 16) c0 = fmaf(mask, wv, c0); else c1 = fmaf(mask, wv, c1);
            }
#pragma unroll
            for (int s2 = 9; s2 < 17; s2++)
                c1 = fmaf(mask, W1[(s2 * 32 + sidx[s2]) * HH + col], c1);
#pragma unroll
            for (int s2 = 17; s2 < 25; s2++)
                c2 = fmaf(mask, W1[(s2 * 32 + sidx[s2]) * HH + col], c2);
            {
                float wv = W1[(25 * 32 + i25) * HH + col];
                if (i25 < 16) c2 = fmaf(mask, wv, c2); else c3 = fmaf(mask, wv, c3);
            }
#pragma unroll
            for (int s2 = 26; s2 < 32; s2++)
                c3 = fmaf(mask, W1[(s2 * 32 + sidx[s2]) * HH + col], c3);
#pragma unroll
            for (int a = 0; a < AA; a++)
                c3 = fmaf(action[((long)b * TT + (t + 1)) * AA + a],
                          W1[(SDIM + a) * HH + col], c3);
            g_x[b * HH + col] = (((c0 + b1[col]) + c1) + c2) + c3;
        }
        __syncthreads();   // protect sidx reuse across units
    }
}

// ---------------- launch ----------------
extern "C" void kernel_launch(void* const* d_in, const int* in_sizes, int n_in,
                              void* d_out, int out_size) {
    (void)in_sizes; (void)n_in; (void)out_size;
    const float* embed     = (const float*)d_in[0];
    const float* action    = (const float*)d_in[1];
    const float* isf       = (const float*)d_in[2];
    const float* W_img_in  = (const float*)d_in[3];
    const float* b_img_in  = (const float*)d_in[4];
    const float* W_ih      = (const float*)d_in[5];
    const float* b_ih      = (const float*)d_in[6];
    const float* W_hh      = (const float*)d_in[7];
    const float* b_hh      = (const float*)d_in[8];
    const float* W_img_out = (const float*)d_in[9];
    const float* b_img_out = (const float*)d_in[10];
    const float* W_obs_out = (const float*)d_in[11];
    const float* b_obs_out = (const float*)d_in[12];
    float* out = (float*)d_out;

    k_init<<<256, 256>>>(action, W_img_in, b_img_in);
    k_pre<<<NQITEMS, 256>>>(embed, W_obs_out);
    for (int t = 0; t < TT; t++) {
        k_step1<<<K1_GEMM + K1_BG, 256>>>(embed, isf, W_ih, b_ih, W_hh, b_hh,
                                          W_obs_out, out, t);
        k_step2<<<K2_GEMM + K2_BG, 256>>>(embed, isf, action,
                                          W_img_in, b_img_in,
                                          W_img_out, b_img_out,
                                          W_obs_out, b_obs_out, out, t);
    }
}